// round 3
// baseline (speedup 1.0000x reference)
#include <cuda_runtime.h>
#include <math.h>

#define BB 2
#define TT 2048
#define CC 768
#define NH 12
#define HD 64

// Scratch (allocation-free rule: __device__ globals)
__device__ float g_q[BB*NH*TT*HD];
__device__ float g_k[BB*NH*TT*HD];
__device__ float g_v[BB*NH*TT*HD];
__device__ float g_att[(size_t)BB*TT*CC];

// ---------------------------------------------------------------------------
// SGEMM 128x128x8, 8x8 micro-tile, 256 threads, register-prefetch pipeline.
// C[m,n] = sum_k A[m,k] * B[n,k]   (both row-major, K contiguous)
// Rows owned by a thread: {4ty+i, 64+4ty+i}; cols: {4tx+j, 64+4tx+j}
// ---------------------------------------------------------------------------
#define GEMM_BODY(A_PTR, B_PTR)                                               \
    __shared__ float As[8 * 128];                                             \
    __shared__ float Bs[8 * 128];                                             \
    const int tx = threadIdx.x, ty = threadIdx.y;                             \
    const int tid = ty * 16 + tx;                                             \
    const int m0 = blockIdx.y * 128, n0 = blockIdx.x * 128;                   \
    const int lr = tid >> 1;  /* 0..127 */                                    \
    const int lq = tid & 1;   /* which float4 of the 8-wide k chunk */        \
    const float* ag = (A_PTR) + (size_t)(m0 + lr) * CC + 4 * lq;              \
    const float* bg = (B_PTR) + (size_t)(n0 + lr) * CC + 4 * lq;              \
    float acc[8][8] = {};                                                     \
    float4 pa = *(const float4*)ag;                                           \
    float4 pb = *(const float4*)bg;                                           \
    for (int k0 = 0; k0 < CC; k0 += 8) {                                      \
        As[(4 * lq + 0) * 128 + lr] = pa.x;                                   \
        As[(4 * lq + 1) * 128 + lr] = pa.y;                                   \
        As[(4 * lq + 2) * 128 + lr] = pa.z;                                   \
        As[(4 * lq + 3) * 128 + lr] = pa.w;                                   \
        Bs[(4 * lq + 0) * 128 + lr] = pb.x;                                   \
        Bs[(4 * lq + 1) * 128 + lr] = pb.y;                                   \
        Bs[(4 * lq + 2) * 128 + lr] = pb.z;                                   \
        Bs[(4 * lq + 3) * 128 + lr] = pb.w;                                   \
        __syncthreads();                                                      \
        if (k0 + 8 < CC) {                                                    \
            pa = *(const float4*)(ag + k0 + 8);                               \
            pb = *(const float4*)(bg + k0 + 8);                               \
        }                                                                     \
        _Pragma("unroll")                                                     \
        for (int kk = 0; kk < 8; kk++) {                                      \
            float a[8], b[8];                                                 \
            *(float4*)(a)     = *(const float4*)&As[kk * 128 + 4 * ty];       \
            *(float4*)(a + 4) = *(const float4*)&As[kk * 128 + 64 + 4 * ty];  \
            *(float4*)(b)     = *(const float4*)&Bs[kk * 128 + 4 * tx];       \
            *(float4*)(b + 4) = *(const float4*)&Bs[kk * 128 + 64 + 4 * tx];  \
            _Pragma("unroll")                                                 \
            for (int i = 0; i < 8; i++)                                       \
                _Pragma("unroll")                                             \
                for (int j = 0; j < 8; j++)                                   \
                    acc[i][j] += a[i] * b[j];                                 \
        }                                                                     \
        __syncthreads();                                                      \
    }

// GEMM1: qkv = x @ W_attn^T, scatter into g_q/g_k/g_v as [B,H,T,D]
__global__ __launch_bounds__(256) void qkv_gemm(const float* __restrict__ X,
                                                const float* __restrict__ W) {
    GEMM_BODY(X, W)
    #pragma unroll
    for (int ii = 0; ii < 8; ii++) {
        int m = m0 + ((ii < 4) ? (4 * ty + ii) : (64 + 4 * ty + ii - 4));
        int b = m >> 11;
        int t = m & 2047;
        #pragma unroll
        for (int jh = 0; jh < 2; jh++) {
            int n = n0 + jh * 64 + 4 * tx;      // 4 contiguous outputs start here
            int sec = n / CC;                   // 0=q 1=k 2=v (4-col group never straddles)
            int c = n - sec * CC;
            int h = c >> 6, d = c & 63;         // d..d+3 contiguous, same head
            float* dst = (sec == 0) ? g_q : ((sec == 1) ? g_k : g_v);
            float4 v4 = make_float4(acc[ii][jh * 4 + 0], acc[ii][jh * 4 + 1],
                                    acc[ii][jh * 4 + 2], acc[ii][jh * 4 + 3]);
            *(float4*)&dst[(size_t)((b * NH + h) * TT + t) * HD + d] = v4;
        }
    }
}

// GEMM2: out = att @ W_proj^T
__global__ __launch_bounds__(256) void proj_gemm(const float* __restrict__ W,
                                                 float* __restrict__ out) {
    GEMM_BODY(g_att, W)
    #pragma unroll
    for (int ii = 0; ii < 8; ii++) {
        int m = m0 + ((ii < 4) ? (4 * ty + ii) : (64 + 4 * ty + ii - 4));
        #pragma unroll
        for (int jh = 0; jh < 2; jh++) {
            int n = n0 + jh * 64 + 4 * tx;
            float4 v4 = make_float4(acc[ii][jh * 4 + 0], acc[ii][jh * 4 + 1],
                                    acc[ii][jh * 4 + 2], acc[ii][jh * 4 + 3]);
            *(float4*)&out[(size_t)m * CC + n] = v4;
        }
    }
}

// ---------------------------------------------------------------------------
// Flash attention: Bq=64, Bk=32, 256 threads, STATIC shared (<48KB, no
// cudaFuncSetAttribute needed). One block = (qtile, bh). Online softmax.
// ---------------------------------------------------------------------------
__global__ __launch_bounds__(256) void attn_kernel() {
    __shared__ float Qs[64 * 65];   // pre-scaled by 1/8
    __shared__ float Ks[32 * 65];
    __shared__ float Vs[32 * 65];   // row = key, col = d
    __shared__ float Ps[64 * 33];

    const int qt = blockIdx.x;
    const int bh = blockIdx.y;
    const int q0 = qt * 64;
    const float* qp = g_q + (size_t)bh * TT * HD;
    const float* kp = g_k + (size_t)bh * TT * HD;
    const float* vp = g_v + (size_t)bh * TT * HD;

    const int tx = threadIdx.x, ty = threadIdx.y;
    const int tid = ty * 16 + tx;
    const float scale = 0.125f;   // 1/sqrt(64)

    // Load Q tile once (pre-scaled), float4 gmem reads
    #pragma unroll
    for (int u = 0; u < 4; u++) {
        int idx = (tid + u * 256) * 4;   // 0..4092
        int r = idx >> 6, c = idx & 63;
        float4 q4 = *(const float4*)&qp[(size_t)(q0 + r) * HD + c];
        Qs[r * 65 + c + 0] = q4.x * scale;
        Qs[r * 65 + c + 1] = q4.y * scale;
        Qs[r * 65 + c + 2] = q4.z * scale;
        Qs[r * 65 + c + 3] = q4.w * scale;
    }

    float mi[4], li[4], acc[4][4];
    #pragma unroll
    for (int i = 0; i < 4; i++) {
        mi[i] = -INFINITY;
        li[i] = 0.0f;
        #pragma unroll
        for (int j = 0; j < 4; j++) acc[i][j] = 0.0f;
    }

    const int nkt = 2 * qt + 2;          // key tiles of 32, covering keys <= q0+63
    for (int kt = 0; kt < nkt; kt++) {
        const int k0 = kt * 32;
        // Load K/V tiles (32x64 each)
        #pragma unroll
        for (int u = 0; u < 2; u++) {
            int idx = (tid + u * 256) * 4;    // 0..2044
            int r = idx >> 6, c = idx & 63;
            float4 k4 = *(const float4*)&kp[(size_t)(k0 + r) * HD + c];
            float4 v4 = *(const float4*)&vp[(size_t)(k0 + r) * HD + c];
            Ks[r * 65 + c + 0] = k4.x; Ks[r * 65 + c + 1] = k4.y;
            Ks[r * 65 + c + 2] = k4.z; Ks[r * 65 + c + 3] = k4.w;
            Vs[r * 65 + c + 0] = v4.x; Vs[r * 65 + c + 1] = v4.y;
            Vs[r * 65 + c + 2] = v4.z; Vs[r * 65 + c + 3] = v4.w;
        }
        __syncthreads();

        // S = Qs @ Ks^T : thread owns rows 4ty..4ty+3, cols 2tx..2tx+1
        float s[4][2] = {};
        #pragma unroll
        for (int kk = 0; kk < 64; kk++) {
            float a[4], b[2];
            #pragma unroll
            for (int i = 0; i < 4; i++) a[i] = Qs[(4 * ty + i) * 65 + kk];
            #pragma unroll
            for (int j = 0; j < 2; j++) b[j] = Ks[(2 * tx + j) * 65 + kk];
            #pragma unroll
            for (int i = 0; i < 4; i++)
                #pragma unroll
                for (int j = 0; j < 2; j++)
                    s[i][j] += a[i] * b[j];
        }

        // Causal mask (only tiles overlapping the diagonal: k0 >= q0)
        if (k0 >= q0) {
            #pragma unroll
            for (int i = 0; i < 4; i++)
                #pragma unroll
                for (int j = 0; j < 2; j++)
                    if (k0 + 2 * tx + j > q0 + 4 * ty + i) s[i][j] = -INFINITY;
        }

        // Online softmax per row (reduce across 16 tx lanes)
        #pragma unroll
        for (int i = 0; i < 4; i++) {
            float rm = fmaxf(s[i][0], s[i][1]);
            #pragma unroll
            for (int o = 8; o > 0; o >>= 1)
                rm = fmaxf(rm, __shfl_xor_sync(0xffffffffu, rm, o, 16));
            float mnew = fmaxf(mi[i], rm);
            float alpha = __expf(mi[i] - mnew);
            float rs = 0.0f;
            #pragma unroll
            for (int j = 0; j < 2; j++) {
                s[i][j] = __expf(s[i][j] - mnew);
                rs += s[i][j];
            }
            #pragma unroll
            for (int o = 8; o > 0; o >>= 1)
                rs += __shfl_xor_sync(0xffffffffu, rs, o, 16);
            li[i] = li[i] * alpha + rs;
            mi[i] = mnew;
            #pragma unroll
            for (int j = 0; j < 4; j++) acc[i][j] *= alpha;
            Ps[(4 * ty + i) * 33 + 2 * tx + 0] = s[i][0];
            Ps[(4 * ty + i) * 33 + 2 * tx + 1] = s[i][1];
        }
        __syncthreads();

        // acc += Ps @ Vs  (thread: rows 4ty.., cols 4tx.., kk over 32 keys)
        #pragma unroll
        for (int kk = 0; kk < 32; kk++) {
            float a[4], b[4];
            #pragma unroll
            for (int i = 0; i < 4; i++) a[i] = Ps[(4 * ty + i) * 33 + kk];
            #pragma unroll
            for (int j = 0; j < 4; j++) b[j] = Vs[kk * 65 + 4 * tx + j];
            #pragma unroll
            for (int i = 0; i < 4; i++)
                #pragma unroll
                for (int j = 0; j < 4; j++)
                    acc[i][j] += a[i] * b[j];
        }
        __syncthreads();
    }

    // Epilogue: normalize and write [B,T,C]
    const int b = bh / NH, h = bh % NH;
    #pragma unroll
    for (int i = 0; i < 4; i++) {
        float inv = 1.0f / li[i];
        int t = q0 + 4 * ty + i;
        float4 v4 = make_float4(acc[i][0] * inv, acc[i][1] * inv,
                                acc[i][2] * inv, acc[i][3] * inv);
        *(float4*)&g_att[(size_t)(b * TT + t) * CC + h * HD + 4 * tx] = v4;
    }
}

// ---------------------------------------------------------------------------
extern "C" void kernel_launch(void* const* d_in, const int* in_sizes, int n_in,
                              void* d_out, int out_size) {
    const float* x  = (const float*)d_in[0];   // [2,2048,768]
    const float* Wa = (const float*)d_in[1];   // [2304,768]
    const float* Wp = (const float*)d_in[2];   // [768,768]
    float* out = (float*)d_out;                // [2,2048,768]

    // QKV: M=4096 (32 tiles), N=2304 (18 tiles)
    qkv_gemm<<<dim3(18, 32), dim3(16, 16)>>>(x, Wa);

    // Attention: 32 q-tiles x 24 (b,h), static smem only
    attn_kernel<<<dim3(32, 24), dim3(16, 16)>>>();

    // Proj: M=4096 (32 tiles), N=768 (6 tiles)
    proj_gemm<<<dim3(6, 32), dim3(16, 16)>>>(Wp, out);
}

// round 5
// speedup vs baseline: 1.1951x; 1.1951x over previous
#include <cuda_runtime.h>
#include <cuda_bf16.h>
#include <math.h>
#include <stdint.h>

#define BB 2
#define TT 2048
#define CC 768
#define NH 12
#define HD 64

// Scratch (allocation-free rule: __device__ globals)
__device__ float g_q[BB*NH*TT*HD];
__device__ float g_k[BB*NH*TT*HD];
__device__ float g_v[BB*NH*TT*HD];
__device__ float g_att[(size_t)BB*TT*CC];

// ---------------------------------------------------------------------------
// mma.sync helpers (HMMA path — works on base sm_100 target)
// ---------------------------------------------------------------------------
__device__ __forceinline__ void mma_bf16(float* d, const uint32_t* a,
                                         const uint32_t* b) {
    asm volatile(
        "mma.sync.aligned.m16n8k16.row.col.f32.bf16.bf16.f32 "
        "{%0,%1,%2,%3}, {%4,%5,%6,%7}, {%8,%9}, {%0,%1,%2,%3};"
        : "+f"(d[0]), "+f"(d[1]), "+f"(d[2]), "+f"(d[3])
        : "r"(a[0]), "r"(a[1]), "r"(a[2]), "r"(a[3]), "r"(b[0]), "r"(b[1]));
}

__device__ __forceinline__ void ldm_x4(uint32_t* r, const void* p) {
    uint32_t addr = (uint32_t)__cvta_generic_to_shared(p);
    asm volatile("ldmatrix.sync.aligned.m8n8.x4.shared.b16 {%0,%1,%2,%3}, [%4];"
                 : "=r"(r[0]), "=r"(r[1]), "=r"(r[2]), "=r"(r[3]) : "r"(addr));
}

__device__ __forceinline__ void ldm_x2(uint32_t* r, const void* p) {
    uint32_t addr = (uint32_t)__cvta_generic_to_shared(p);
    asm volatile("ldmatrix.sync.aligned.m8n8.x2.shared.b16 {%0,%1}, [%2];"
                 : "=r"(r[0]), "=r"(r[1]) : "r"(addr));
}

// ---------------------------------------------------------------------------
// HMMA GEMM: C[m,n] = sum_k A[m,k]*B[n,k]. Block 128x128, 8 warps (64x32 each),
// K-chunk 16, bf16 hi/lo split x3 terms, fp32 accumulate.
// smem rows padded to 24 bf16 (48B) -> conflict-free ldmatrix.
// ---------------------------------------------------------------------------
#define SMP 24

#define TC_GEMM_BODY(A_PTR, B_PTR)                                            \
    __shared__ __nv_bfloat16 sAh[128 * SMP], sAl[128 * SMP];                  \
    __shared__ __nv_bfloat16 sBh[128 * SMP], sBl[128 * SMP];                  \
    const int tid = threadIdx.x;                                              \
    const int wid = tid >> 5, lane = tid & 31;                                \
    const int m0 = blockIdx.y * 128, n0 = blockIdx.x * 128;                   \
    const int wm = (wid & 1) * 64;                                            \
    const int wn = (wid >> 1) * 32;                                           \
    float acc[4][4][4];                                                       \
    _Pragma("unroll")                                                         \
    for (int i = 0; i < 4; i++)                                               \
        _Pragma("unroll")                                                     \
        for (int j = 0; j < 4; j++)                                           \
            _Pragma("unroll")                                                 \
            for (int e = 0; e < 4; e++) acc[i][j][e] = 0.0f;                  \
    const int lrow = tid >> 2;        /* 0..63 */                             \
    const int lseg = (tid & 3) * 4;   /* 0,4,8,12 */                          \
    _Pragma("unroll 1")                                                       \
    for (int k0 = 0; k0 < CC; k0 += 16) {                                     \
        _Pragma("unroll")                                                     \
        for (int u = 0; u < 2; u++) {                                         \
            int row = lrow + u * 64;                                          \
            float4 va = *(const float4*)((A_PTR) + (size_t)(m0 + row) * CC + k0 + lseg); \
            float4 vb = *(const float4*)((B_PTR) + (size_t)(n0 + row) * CC + k0 + lseg); \
            float fa[4] = {va.x, va.y, va.z, va.w};                           \
            float fb[4] = {vb.x, vb.y, vb.z, vb.w};                           \
            _Pragma("unroll")                                                 \
            for (int e = 0; e < 4; e++) {                                     \
                __nv_bfloat16 h = __float2bfloat16_rn(fa[e]);                 \
                sAh[row * SMP + lseg + e] = h;                                \
                sAl[row * SMP + lseg + e] =                                   \
                    __float2bfloat16_rn(fa[e] - __bfloat162float(h));         \
                __nv_bfloat16 g = __float2bfloat16_rn(fb[e]);                 \
                sBh[row * SMP + lseg + e] = g;                                \
                sBl[row * SMP + lseg + e] =                                   \
                    __float2bfloat16_rn(fb[e] - __bfloat162float(g));         \
            }                                                                 \
        }                                                                     \
        __syncthreads();                                                      \
        /* B fragments: 4 n-tiles, hi+lo */                                   \
        uint32_t fbh[4][2], fbl[4][2];                                        \
        {                                                                     \
            int r = lane & 7, ms = (lane >> 3) & 1;                           \
            _Pragma("unroll")                                                 \
            for (int nt = 0; nt < 4; nt++) {                                  \
                const __nv_bfloat16* bp =                                     \
                    &sBh[(wn + nt * 8 + r) * SMP + ms * 8];                   \
                ldm_x2(fbh[nt], bp);                                          \
                ldm_x2(fbl[nt], &sBl[(wn + nt * 8 + r) * SMP + ms * 8]);      \
            }                                                                 \
        }                                                                     \
        /* A fragments + MMAs */                                              \
        {                                                                     \
            int mat = lane >> 3, r = lane & 7;                                \
            int arow_off = (mat & 1) * 8 + r;                                 \
            int acol = (mat >> 1) * 8;                                        \
            _Pragma("unroll")                                                 \
            for (int mt = 0; mt < 4; mt++) {                                  \
                uint32_t fah[4], fal[4];                                      \
                int arow = wm + mt * 16 + arow_off;                           \
                ldm_x4(fah, &sAh[arow * SMP + acol]);                         \
                ldm_x4(fal, &sAl[arow * SMP + acol]);                         \
                _Pragma("unroll")                                             \
                for (int nt = 0; nt < 4; nt++) {                              \
                    mma_bf16(acc[mt][nt], fah, fbh[nt]);                      \
                    mma_bf16(acc[mt][nt], fah, fbl[nt]);                      \
                    mma_bf16(acc[mt][nt], fal, fbh[nt]);                      \
                }                                                             \
            }                                                                 \
        }                                                                     \
        __syncthreads();                                                      \
    }

// GEMM1: qkv = x @ W_attn^T, scatter into g_q/g_k/g_v as [B,H,T,D]
__global__ __launch_bounds__(256) void qkv_gemm(const float* __restrict__ X,
                                                const float* __restrict__ W) {
    TC_GEMM_BODY(X, W)
    #pragma unroll
    for (int mt = 0; mt < 4; mt++) {
        #pragma unroll
        for (int nt = 0; nt < 4; nt++) {
            int n = n0 + wn + nt * 8 + (lane & 3) * 2;
            int sec = n / CC;               // 0=q 1=k 2=v
            int c2 = n - sec * CC;
            int h = c2 >> 6, d = c2 & 63;
            float* dst = (sec == 0) ? g_q : ((sec == 1) ? g_k : g_v);
            #pragma unroll
            for (int half = 0; half < 2; half++) {
                int m = m0 + wm + mt * 16 + (lane >> 2) + half * 8;
                int b = m >> 11, t = m & 2047;
                float2 v2 = make_float2(acc[mt][nt][half * 2 + 0],
                                        acc[mt][nt][half * 2 + 1]);
                *(float2*)&dst[(size_t)((b * NH + h) * TT + t) * HD + d] = v2;
            }
        }
    }
}

// GEMM2: out = att @ W_proj^T
__global__ __launch_bounds__(256) void proj_gemm(const float* __restrict__ W,
                                                 float* __restrict__ out) {
    TC_GEMM_BODY(g_att, W)
    #pragma unroll
    for (int mt = 0; mt < 4; mt++) {
        #pragma unroll
        for (int nt = 0; nt < 4; nt++) {
            int n = n0 + wn + nt * 8 + (lane & 3) * 2;
            #pragma unroll
            for (int half = 0; half < 2; half++) {
                int m = m0 + wm + mt * 16 + (lane >> 2) + half * 8;
                float2 v2 = make_float2(acc[mt][nt][half * 2 + 0],
                                        acc[mt][nt][half * 2 + 1]);
                *(float2*)&out[(size_t)m * CC + n] = v2;
            }
        }
    }
}

// ---------------------------------------------------------------------------
// Flash attention: Bq=64, Bk=32, 256 threads, static shared (<48KB).
// One block = (qtile, bh). Online softmax. (unchanged from R3 passing kernel)
// ---------------------------------------------------------------------------
__global__ __launch_bounds__(256) void attn_kernel() {
    __shared__ float Qs[64 * 65];   // pre-scaled by 1/8
    __shared__ float Ks[32 * 65];
    __shared__ float Vs[32 * 65];   // row = key, col = d
    __shared__ float Ps[64 * 33];

    const int qt = blockIdx.x;
    const int bh = blockIdx.y;
    const int q0 = qt * 64;
    const float* qp = g_q + (size_t)bh * TT * HD;
    const float* kp = g_k + (size_t)bh * TT * HD;
    const float* vp = g_v + (size_t)bh * TT * HD;

    const int tx = threadIdx.x, ty = threadIdx.y;
    const int tid = ty * 16 + tx;
    const float scale = 0.125f;   // 1/sqrt(64)

    #pragma unroll
    for (int u = 0; u < 4; u++) {
        int idx = (tid + u * 256) * 4;   // 0..4092
        int r = idx >> 6, c = idx & 63;
        float4 q4 = *(const float4*)&qp[(size_t)(q0 + r) * HD + c];
        Qs[r * 65 + c + 0] = q4.x * scale;
        Qs[r * 65 + c + 1] = q4.y * scale;
        Qs[r * 65 + c + 2] = q4.z * scale;
        Qs[r * 65 + c + 3] = q4.w * scale;
    }

    float mi[4], li[4], acc[4][4];
    #pragma unroll
    for (int i = 0; i < 4; i++) {
        mi[i] = -INFINITY;
        li[i] = 0.0f;
        #pragma unroll
        for (int j = 0; j < 4; j++) acc[i][j] = 0.0f;
    }

    const int nkt = 2 * qt + 2;
    for (int kt = 0; kt < nkt; kt++) {
        const int k0 = kt * 32;
        #pragma unroll
        for (int u = 0; u < 2; u++) {
            int idx = (tid + u * 256) * 4;
            int r = idx >> 6, c = idx & 63;
            float4 k4 = *(const float4*)&kp[(size_t)(k0 + r) * HD + c];
            float4 v4 = *(const float4*)&vp[(size_t)(k0 + r) * HD + c];
            Ks[r * 65 + c + 0] = k4.x; Ks[r * 65 + c + 1] = k4.y;
            Ks[r * 65 + c + 2] = k4.z; Ks[r * 65 + c + 3] = k4.w;
            Vs[r * 65 + c + 0] = v4.x; Vs[r * 65 + c + 1] = v4.y;
            Vs[r * 65 + c + 2] = v4.z; Vs[r * 65 + c + 3] = v4.w;
        }
        __syncthreads();

        float s[4][2] = {};
        #pragma unroll
        for (int kk = 0; kk < 64; kk++) {
            float a[4], b[2];
            #pragma unroll
            for (int i = 0; i < 4; i++) a[i] = Qs[(4 * ty + i) * 65 + kk];
            #pragma unroll
            for (int j = 0; j < 2; j++) b[j] = Ks[(2 * tx + j) * 65 + kk];
            #pragma unroll
            for (int i = 0; i < 4; i++)
                #pragma unroll
                for (int j = 0; j < 2; j++)
                    s[i][j] += a[i] * b[j];
        }

        if (k0 >= q0) {
            #pragma unroll
            for (int i = 0; i < 4; i++)
                #pragma unroll
                for (int j = 0; j < 2; j++)
                    if (k0 + 2 * tx + j > q0 + 4 * ty + i) s[i][j] = -INFINITY;
        }

        #pragma unroll
        for (int i = 0; i < 4; i++) {
            float rm = fmaxf(s[i][0], s[i][1]);
            #pragma unroll
            for (int o = 8; o > 0; o >>= 1)
                rm = fmaxf(rm, __shfl_xor_sync(0xffffffffu, rm, o, 16));
            float mnew = fmaxf(mi[i], rm);
            float alpha = __expf(mi[i] - mnew);
            float rs = 0.0f;
            #pragma unroll
            for (int j = 0; j < 2; j++) {
                s[i][j] = __expf(s[i][j] - mnew);
                rs += s[i][j];
            }
            #pragma unroll
            for (int o = 8; o > 0; o >>= 1)
                rs += __shfl_xor_sync(0xffffffffu, rs, o, 16);
            li[i] = li[i] * alpha + rs;
            mi[i] = mnew;
            #pragma unroll
            for (int j = 0; j < 4; j++) acc[i][j] *= alpha;
            Ps[(4 * ty + i) * 33 + 2 * tx + 0] = s[i][0];
            Ps[(4 * ty + i) * 33 + 2 * tx + 1] = s[i][1];
        }
        __syncthreads();

        #pragma unroll
        for (int kk = 0; kk < 32; kk++) {
            float a[4], b[4];
            #pragma unroll
            for (int i = 0; i < 4; i++) a[i] = Ps[(4 * ty + i) * 33 + kk];
            #pragma unroll
            for (int j = 0; j < 4; j++) b[j] = Vs[kk * 65 + 4 * tx + j];
            #pragma unroll
            for (int i = 0; i < 4; i++)
                #pragma unroll
                for (int j = 0; j < 4; j++)
                    acc[i][j] += a[i] * b[j];
        }
        __syncthreads();
    }

    const int b = bh / NH, h = bh % NH;
    #pragma unroll
    for (int i = 0; i < 4; i++) {
        float inv = 1.0f / li[i];
        int t = q0 + 4 * ty + i;
        float4 v4 = make_float4(acc[i][0] * inv, acc[i][1] * inv,
                                acc[i][2] * inv, acc[i][3] * inv);
        *(float4*)&g_att[(size_t)(b * TT + t) * CC + h * HD + 4 * tx] = v4;
    }
}

// ---------------------------------------------------------------------------
extern "C" void kernel_launch(void* const* d_in, const int* in_sizes, int n_in,
                              void* d_out, int out_size) {
    const float* x  = (const float*)d_in[0];   // [2,2048,768]
    const float* Wa = (const float*)d_in[1];   // [2304,768]
    const float* Wp = (const float*)d_in[2];   // [768,768]
    float* out = (float*)d_out;                // [2,2048,768]

    // QKV: M=4096 (32 tiles), N=2304 (18 tiles)
    qkv_gemm<<<dim3(18, 32), 256>>>(x, Wa);

    // Attention: 32 q-tiles x 24 (b,h), static smem only
    attn_kernel<<<dim3(32, 24), dim3(16, 16)>>>();

    // Proj: M=4096 (32 tiles), N=768 (6 tiles)
    proj_gemm<<<dim3(6, 32), 256>>>(Wp, out);
}

// round 6
// speedup vs baseline: 1.8181x; 1.5212x over previous
#include <cuda_runtime.h>
#include <cuda_bf16.h>
#include <math.h>
#include <stdint.h>

#define BB 2
#define TT 2048
#define CC 768
#define NH 12
#define HD 64

// Scratch (allocation-free rule: __device__ globals)
__device__ float g_q[BB*NH*TT*HD];
__device__ float g_k[BB*NH*TT*HD];
__device__ float g_v[BB*NH*TT*HD];
__device__ float g_att[(size_t)BB*TT*CC];

// ---------------------------------------------------------------------------
// mma.sync helpers (HMMA path — works on base sm_100 target)
// ---------------------------------------------------------------------------
__device__ __forceinline__ void mma_bf16(float* d, const uint32_t* a,
                                         const uint32_t* b) {
    asm volatile(
        "mma.sync.aligned.m16n8k16.row.col.f32.bf16.bf16.f32 "
        "{%0,%1,%2,%3}, {%4,%5,%6,%7}, {%8,%9}, {%0,%1,%2,%3};"
        : "+f"(d[0]), "+f"(d[1]), "+f"(d[2]), "+f"(d[3])
        : "r"(a[0]), "r"(a[1]), "r"(a[2]), "r"(a[3]), "r"(b[0]), "r"(b[1]));
}

__device__ __forceinline__ void ldm_x4(uint32_t* r, const void* p) {
    uint32_t addr = (uint32_t)__cvta_generic_to_shared(p);
    asm volatile("ldmatrix.sync.aligned.m8n8.x4.shared.b16 {%0,%1,%2,%3}, [%4];"
                 : "=r"(r[0]), "=r"(r[1]), "=r"(r[2]), "=r"(r[3]) : "r"(addr));
}

__device__ __forceinline__ void ldm_x2(uint32_t* r, const void* p) {
    uint32_t addr = (uint32_t)__cvta_generic_to_shared(p);
    asm volatile("ldmatrix.sync.aligned.m8n8.x2.shared.b16 {%0,%1}, [%2];"
                 : "=r"(r[0]), "=r"(r[1]) : "r"(addr));
}

__device__ __forceinline__ void ldm_x2_trans(uint32_t* r, const void* p) {
    uint32_t addr = (uint32_t)__cvta_generic_to_shared(p);
    asm volatile("ldmatrix.sync.aligned.m8n8.x2.trans.shared.b16 {%0,%1}, [%2];"
                 : "=r"(r[0]), "=r"(r[1]) : "r"(addr));
}

// Split (x,y) into packed bf16x2 hi and lo (x in low half)
__device__ __forceinline__ void split2(float x, float y, uint32_t& hi, uint32_t& lo) {
    __nv_bfloat16 hx = __float2bfloat16_rn(x);
    __nv_bfloat16 hy = __float2bfloat16_rn(y);
    __nv_bfloat162 h2(hx, hy);
    __nv_bfloat162 l2(__float2bfloat16_rn(x - __bfloat162float(hx)),
                      __float2bfloat16_rn(y - __bfloat162float(hy)));
    hi = *(uint32_t*)&h2;
    lo = *(uint32_t*)&l2;
}

// ---------------------------------------------------------------------------
// HMMA GEMM: C[m,n] = sum_k A[m,k]*B[n,k]. Block 128x128, 8 warps (64x32 each),
// K-chunk 16, bf16 hi/lo split x3 terms, fp32 accumulate. (unchanged from R5)
// ---------------------------------------------------------------------------
#define SMP 24

#define TC_GEMM_BODY(A_PTR, B_PTR)                                            \
    __shared__ __nv_bfloat16 sAh[128 * SMP], sAl[128 * SMP];                  \
    __shared__ __nv_bfloat16 sBh[128 * SMP], sBl[128 * SMP];                  \
    const int tid = threadIdx.x;                                              \
    const int wid = tid >> 5, lane = tid & 31;                                \
    const int m0 = blockIdx.y * 128, n0 = blockIdx.x * 128;                   \
    const int wm = (wid & 1) * 64;                                            \
    const int wn = (wid >> 1) * 32;                                           \
    float acc[4][4][4];                                                       \
    _Pragma("unroll")                                                         \
    for (int i = 0; i < 4; i++)                                               \
        _Pragma("unroll")                                                     \
        for (int j = 0; j < 4; j++)                                           \
            _Pragma("unroll")                                                 \
            for (int e = 0; e < 4; e++) acc[i][j][e] = 0.0f;                  \
    const int lrow = tid >> 2;        /* 0..63 */                             \
    const int lseg = (tid & 3) * 4;   /* 0,4,8,12 */                          \
    _Pragma("unroll 1")                                                       \
    for (int k0 = 0; k0 < CC; k0 += 16) {                                     \
        _Pragma("unroll")                                                     \
        for (int u = 0; u < 2; u++) {                                         \
            int row = lrow + u * 64;                                          \
            float4 va = *(const float4*)((A_PTR) + (size_t)(m0 + row) * CC + k0 + lseg); \
            float4 vb = *(const float4*)((B_PTR) + (size_t)(n0 + row) * CC + k0 + lseg); \
            float fa[4] = {va.x, va.y, va.z, va.w};                           \
            float fb[4] = {vb.x, vb.y, vb.z, vb.w};                           \
            _Pragma("unroll")                                                 \
            for (int e = 0; e < 4; e++) {                                     \
                __nv_bfloat16 h = __float2bfloat16_rn(fa[e]);                 \
                sAh[row * SMP + lseg + e] = h;                                \
                sAl[row * SMP + lseg + e] =                                   \
                    __float2bfloat16_rn(fa[e] - __bfloat162float(h));         \
                __nv_bfloat16 g = __float2bfloat16_rn(fb[e]);                 \
                sBh[row * SMP + lseg + e] = g;                                \
                sBl[row * SMP + lseg + e] =                                   \
                    __float2bfloat16_rn(fb[e] - __bfloat162float(g));         \
            }                                                                 \
        }                                                                     \
        __syncthreads();                                                      \
        uint32_t fbh[4][2], fbl[4][2];                                        \
        {                                                                     \
            int r = lane & 7, ms = (lane >> 3) & 1;                           \
            _Pragma("unroll")                                                 \
            for (int nt = 0; nt < 4; nt++) {                                  \
                ldm_x2(fbh[nt], &sBh[(wn + nt * 8 + r) * SMP + ms * 8]);      \
                ldm_x2(fbl[nt], &sBl[(wn + nt * 8 + r) * SMP + ms * 8]);      \
            }                                                                 \
        }                                                                     \
        {                                                                     \
            int mat = lane >> 3, r = lane & 7;                                \
            int arow_off = (mat & 1) * 8 + r;                                 \
            int acol = (mat >> 1) * 8;                                        \
            _Pragma("unroll")                                                 \
            for (int mt = 0; mt < 4; mt++) {                                  \
                uint32_t fah[4], fal[4];                                      \
                int arow = wm + mt * 16 + arow_off;                           \
                ldm_x4(fah, &sAh[arow * SMP + acol]);                         \
                ldm_x4(fal, &sAl[arow * SMP + acol]);                         \
                _Pragma("unroll")                                             \
                for (int nt = 0; nt < 4; nt++) {                              \
                    mma_bf16(acc[mt][nt], fah, fbh[nt]);                      \
                    mma_bf16(acc[mt][nt], fah, fbl[nt]);                      \
                    mma_bf16(acc[mt][nt], fal, fbh[nt]);                      \
                }                                                             \
            }                                                                 \
        }                                                                     \
        __syncthreads();                                                      \
    }

// GEMM1: qkv = x @ W_attn^T, scatter into g_q/g_k/g_v as [B,H,T,D]
__global__ __launch_bounds__(256) void qkv_gemm(const float* __restrict__ X,
                                                const float* __restrict__ W) {
    TC_GEMM_BODY(X, W)
    #pragma unroll
    for (int mt = 0; mt < 4; mt++) {
        #pragma unroll
        for (int nt = 0; nt < 4; nt++) {
            int n = n0 + wn + nt * 8 + (lane & 3) * 2;
            int sec = n / CC;               // 0=q 1=k 2=v
            int c2 = n - sec * CC;
            int h = c2 >> 6, d = c2 & 63;
            float* dst = (sec == 0) ? g_q : ((sec == 1) ? g_k : g_v);
            #pragma unroll
            for (int half = 0; half < 2; half++) {
                int m = m0 + wm + mt * 16 + (lane >> 2) + half * 8;
                int b = m >> 11, t = m & 2047;
                float2 v2 = make_float2(acc[mt][nt][half * 2 + 0],
                                        acc[mt][nt][half * 2 + 1]);
                *(float2*)&dst[(size_t)((b * NH + h) * TT + t) * HD + d] = v2;
            }
        }
    }
}

// GEMM2: out = att @ W_proj^T
__global__ __launch_bounds__(256) void proj_gemm(const float* __restrict__ W,
                                                 float* __restrict__ out) {
    TC_GEMM_BODY(g_att, W)
    #pragma unroll
    for (int mt = 0; mt < 4; mt++) {
        #pragma unroll
        for (int nt = 0; nt < 4; nt++) {
            int n = n0 + wn + nt * 8 + (lane & 3) * 2;
            #pragma unroll
            for (int half = 0; half < 2; half++) {
                int m = m0 + wm + mt * 16 + (lane >> 2) + half * 8;
                float2 v2 = make_float2(acc[mt][nt][half * 2 + 0],
                                        acc[mt][nt][half * 2 + 1]);
                *(float2*)&out[(size_t)m * CC + n] = v2;
            }
        }
    }
}

// ---------------------------------------------------------------------------
// HMMA flash attention: Bq=64 (4 warps x 16 rows), Bk=64, bf16 hi/lo split.
// Q fragments direct from gmem; K/V split once per block into smem; S and P
// live in register fragments; online softmax on C-fragments.
// ---------------------------------------------------------------------------
#define ATP 72   // smem row stride (bf16), pad for conflict-free ldmatrix

__global__ __launch_bounds__(128) void attn_kernel() {
    __shared__ __nv_bfloat16 sKh[64 * ATP], sKl[64 * ATP];
    __shared__ __nv_bfloat16 sVh[64 * ATP], sVl[64 * ATP];

    const int qt = gridDim.x - 1 - blockIdx.x;   // heavy blocks first
    const int bh = blockIdx.y;
    const int q0 = qt * 64;
    const int tid = threadIdx.x;
    const int warp = tid >> 5, lane = tid & 31;
    const float* qp = g_q + (size_t)bh * TT * HD;
    const float* kp = g_k + (size_t)bh * TT * HD;
    const float* vp = g_v + (size_t)bh * TT * HD;

    const int r = lane >> 2;          // C/A fragment row
    const int c2 = (lane & 3) * 2;    // C/A fragment col pair
    const float QS = 0.125f;          // 1/sqrt(64)

    // Q fragments (A-layout, 4 k-chunks over HD=64), hi/lo, loaded directly
    uint32_t qfh[4][4], qfl[4][4];
    #pragma unroll
    for (int kc = 0; kc < 4; kc++) {
        #pragma unroll
        for (int e = 0; e < 4; e++) {
            int row = q0 + warp * 16 + r + ((e & 1) ? 8 : 0);
            int col = kc * 16 + c2 + ((e & 2) ? 8 : 0);
            float2 v = *(const float2*)&qp[(size_t)row * HD + col];
            split2(v.x * QS, v.y * QS, qfh[kc][e], qfl[kc][e]);
        }
    }

    float mi[2] = {-1e30f, -1e30f};
    float li[2] = {0.0f, 0.0f};
    float o[8][4];
    #pragma unroll
    for (int nt = 0; nt < 8; nt++)
        #pragma unroll
        for (int e = 0; e < 4; e++) o[nt][e] = 0.0f;

    const int frow = tid >> 1;          // smem fill: row 0..63
    const int fcb  = (tid & 1) * 32;    // col half

    for (int kt = 0; kt <= qt; kt++) {
        const int k0 = kt * 64;

        // ---- convert K/V tile to bf16 hi/lo in smem (once per block) ----
        {
            const float* krow = &kp[(size_t)(k0 + frow) * HD + fcb];
            const float* vrow = &vp[(size_t)(k0 + frow) * HD + fcb];
            #pragma unroll
            for (int u = 0; u < 8; u++) {
                float4 kv = *(const float4*)&krow[u * 4];
                float4 vv = *(const float4*)&vrow[u * 4];
                uint32_t h0, l0, h1, l1;
                split2(kv.x, kv.y, h0, l0);
                split2(kv.z, kv.w, h1, l1);
                *(uint32_t*)&sKh[frow * ATP + fcb + u * 4]     = h0;
                *(uint32_t*)&sKh[frow * ATP + fcb + u * 4 + 2] = h1;
                *(uint32_t*)&sKl[frow * ATP + fcb + u * 4]     = l0;
                *(uint32_t*)&sKl[frow * ATP + fcb + u * 4 + 2] = l1;
                split2(vv.x, vv.y, h0, l0);
                split2(vv.z, vv.w, h1, l1);
                *(uint32_t*)&sVh[frow * ATP + fcb + u * 4]     = h0;
                *(uint32_t*)&sVh[frow * ATP + fcb + u * 4 + 2] = h1;
                *(uint32_t*)&sVl[frow * ATP + fcb + u * 4]     = l0;
                *(uint32_t*)&sVl[frow * ATP + fcb + u * 4 + 2] = l1;
            }
        }
        __syncthreads();

        // ---- S = Q @ K^T (8 key n-tiles x 4 d-chunks x 3 split terms) ----
        float s[8][4];
        #pragma unroll
        for (int nt = 0; nt < 8; nt++)
            #pragma unroll
            for (int e = 0; e < 4; e++) s[nt][e] = 0.0f;

        {
            const int br = lane & 7, ms = (lane >> 3) & 1;
            #pragma unroll
            for (int nt = 0; nt < 8; nt++) {
                #pragma unroll
                for (int kc = 0; kc < 4; kc++) {
                    uint32_t kh[2], kl[2];
                    ldm_x2(kh, &sKh[(nt * 8 + br) * ATP + kc * 16 + ms * 8]);
                    ldm_x2(kl, &sKl[(nt * 8 + br) * ATP + kc * 16 + ms * 8]);
                    mma_bf16(s[nt], qfh[kc], kh);
                    mma_bf16(s[nt], qfh[kc], kl);
                    mma_bf16(s[nt], qfl[kc], kh);
                }
            }
        }

        // ---- causal mask on diagonal tile ----
        if (kt == qt) {
            const int row0 = q0 + warp * 16 + r;
            #pragma unroll
            for (int nt = 0; nt < 8; nt++) {
                int colb = k0 + nt * 8 + c2;
                if (colb     > row0)     s[nt][0] = -1e30f;
                if (colb + 1 > row0)     s[nt][1] = -1e30f;
                if (colb     > row0 + 8) s[nt][2] = -1e30f;
                if (colb + 1 > row0 + 8) s[nt][3] = -1e30f;
            }
        }

        // ---- online softmax (2 rows per thread; quad shfl reductions) ----
        #pragma unroll
        for (int h = 0; h < 2; h++) {
            float m = -1e30f;
            #pragma unroll
            for (int nt = 0; nt < 8; nt++)
                m = fmaxf(m, fmaxf(s[nt][h * 2], s[nt][h * 2 + 1]));
            m = fmaxf(m, __shfl_xor_sync(0xffffffffu, m, 1));
            m = fmaxf(m, __shfl_xor_sync(0xffffffffu, m, 2));
            float mnew = fmaxf(mi[h], m);
            float alpha = __expf(mi[h] - mnew);
            float sum = 0.0f;
            #pragma unroll
            for (int nt = 0; nt < 8; nt++) {
                s[nt][h * 2]     = __expf(s[nt][h * 2] - mnew);
                s[nt][h * 2 + 1] = __expf(s[nt][h * 2 + 1] - mnew);
                sum += s[nt][h * 2] + s[nt][h * 2 + 1];
            }
            sum += __shfl_xor_sync(0xffffffffu, sum, 1);
            sum += __shfl_xor_sync(0xffffffffu, sum, 2);
            li[h] = li[h] * alpha + sum;
            mi[h] = mnew;
            #pragma unroll
            for (int nt = 0; nt < 8; nt++) {
                o[nt][h * 2]     *= alpha;
                o[nt][h * 2 + 1] *= alpha;
            }
        }

        // ---- P to A-fragments (C-layout == A-layout), hi/lo split ----
        uint32_t pfh[4][4], pfl[4][4];
        #pragma unroll
        for (int kc = 0; kc < 4; kc++) {
            split2(s[2 * kc][0],     s[2 * kc][1],     pfh[kc][0], pfl[kc][0]);
            split2(s[2 * kc][2],     s[2 * kc][3],     pfh[kc][1], pfl[kc][1]);
            split2(s[2 * kc + 1][0], s[2 * kc + 1][1], pfh[kc][2], pfl[kc][2]);
            split2(s[2 * kc + 1][2], s[2 * kc + 1][3], pfh[kc][3], pfl[kc][3]);
        }

        // ---- O += P @ V (8 d n-tiles x 4 key-chunks x 3 split terms) ----
        {
            const int vr = lane & 15;
            #pragma unroll
            for (int nt = 0; nt < 8; nt++) {
                #pragma unroll
                for (int kc = 0; kc < 4; kc++) {
                    uint32_t vh[2], vl[2];
                    ldm_x2_trans(vh, &sVh[(kc * 16 + vr) * ATP + nt * 8]);
                    ldm_x2_trans(vl, &sVl[(kc * 16 + vr) * ATP + nt * 8]);
                    mma_bf16(o[nt], pfh[kc], vh);
                    mma_bf16(o[nt], pfh[kc], vl);
                    mma_bf16(o[nt], pfl[kc], vh);
                }
            }
        }
        __syncthreads();
    }

    // ---- epilogue: normalize, write [B,T,C] ----
    const int b = bh / NH, head = bh % NH;
    #pragma unroll
    for (int h = 0; h < 2; h++) {
        float inv = 1.0f / li[h];
        int row = q0 + warp * 16 + r + h * 8;
        float* dst = &g_att[(size_t)(b * TT + row) * CC + head * HD];
        #pragma unroll
        for (int nt = 0; nt < 8; nt++) {
            float2 v2 = make_float2(o[nt][h * 2] * inv, o[nt][h * 2 + 1] * inv);
            *(float2*)&dst[nt * 8 + c2] = v2;
        }
    }
}

// ---------------------------------------------------------------------------
extern "C" void kernel_launch(void* const* d_in, const int* in_sizes, int n_in,
                              void* d_out, int out_size) {
    const float* x  = (const float*)d_in[0];   // [2,2048,768]
    const float* Wa = (const float*)d_in[1];   // [2304,768]
    const float* Wp = (const float*)d_in[2];   // [768,768]
    float* out = (float*)d_out;                // [2,2048,768]

    // QKV: M=4096 (32 tiles), N=2304 (18 tiles)
    qkv_gemm<<<dim3(18, 32), 256>>>(x, Wa);

    // Attention: 32 q-tiles x 24 (b,h)
    attn_kernel<<<dim3(32, 24), 128>>>();

    // Proj: M=4096 (32 tiles), N=768 (6 tiles)
    proj_gemm<<<dim3(6, 32), 256>>>(Wp, out);
}

// round 7
// speedup vs baseline: 2.2312x; 1.2272x over previous
#include <cuda_runtime.h>
#include <cuda_bf16.h>
#include <math.h>
#include <stdint.h>

#define BB 2
#define TT 2048
#define CC 768
#define NH 12
#define HD 64
#define MQ (BB*TT)   // 4096

// Scratch (allocation-free rule: __device__ globals)
__device__ float g_q[BB*NH*TT*HD];
__device__ __nv_bfloat16 g_kh[BB*NH*TT*HD], g_kl[BB*NH*TT*HD];
__device__ __nv_bfloat16 g_vh[BB*NH*TT*HD], g_vl[BB*NH*TT*HD];
__device__ __nv_bfloat16 g_ath[(size_t)BB*TT*CC], g_atl[(size_t)BB*TT*CC];
__device__ __nv_bfloat16 gXh[MQ*CC],     gXl[MQ*CC];
__device__ __nv_bfloat16 gWah[3*CC*CC],  gWal[3*CC*CC];
__device__ __nv_bfloat16 gWph[CC*CC],    gWpl[CC*CC];

// ---------------------------------------------------------------------------
// helpers
// ---------------------------------------------------------------------------
__device__ __forceinline__ void mma_bf16(float* d, const uint32_t* a,
                                         const uint32_t* b) {
    asm volatile(
        "mma.sync.aligned.m16n8k16.row.col.f32.bf16.bf16.f32 "
        "{%0,%1,%2,%3}, {%4,%5,%6,%7}, {%8,%9}, {%0,%1,%2,%3};"
        : "+f"(d[0]), "+f"(d[1]), "+f"(d[2]), "+f"(d[3])
        : "r"(a[0]), "r"(a[1]), "r"(a[2]), "r"(a[3]), "r"(b[0]), "r"(b[1]));
}

__device__ __forceinline__ void ldm_x4(uint32_t* r, const void* p) {
    uint32_t addr = (uint32_t)__cvta_generic_to_shared(p);
    asm volatile("ldmatrix.sync.aligned.m8n8.x4.shared.b16 {%0,%1,%2,%3}, [%4];"
                 : "=r"(r[0]), "=r"(r[1]), "=r"(r[2]), "=r"(r[3]) : "r"(addr));
}

__device__ __forceinline__ void ldm_x2_trans(uint32_t* r, const void* p) {
    uint32_t addr = (uint32_t)__cvta_generic_to_shared(p);
    asm volatile("ldmatrix.sync.aligned.m8n8.x2.trans.shared.b16 {%0,%1}, [%2];"
                 : "=r"(r[0]), "=r"(r[1]) : "r"(addr));
}

// Split (x,y) into packed bf16x2 hi and lo (x in low half)
__device__ __forceinline__ void split2(float x, float y, uint32_t& hi, uint32_t& lo) {
    __nv_bfloat16 hx = __float2bfloat16_rn(x);
    __nv_bfloat16 hy = __float2bfloat16_rn(y);
    __nv_bfloat162 h2(hx, hy);
    __nv_bfloat162 l2(__float2bfloat16_rn(x - __bfloat162float(hx)),
                      __float2bfloat16_rn(y - __bfloat162float(hy)));
    hi = *(uint32_t*)&h2;
    lo = *(uint32_t*)&l2;
}

// ---------------------------------------------------------------------------
// Pre-pass: split fp32 -> bf16 hi/lo
// ---------------------------------------------------------------------------
__global__ __launch_bounds__(256) void split_pass(const float* __restrict__ src,
                                                  __nv_bfloat16* __restrict__ dh,
                                                  __nv_bfloat16* __restrict__ dl,
                                                  int n4) {
    int i = blockIdx.x * 256 + threadIdx.x;
    if (i < n4) {
        float4 v = ((const float4*)src)[i];
        uint32_t h0, l0, h1, l1;
        split2(v.x, v.y, h0, l0);
        split2(v.z, v.w, h1, l1);
        ((uint32_t*)dh)[i * 2]     = h0;
        ((uint32_t*)dh)[i * 2 + 1] = h1;
        ((uint32_t*)dl)[i * 2]     = l0;
        ((uint32_t*)dl)[i * 2 + 1] = l1;
    }
}

// ---------------------------------------------------------------------------
// HMMA GEMM on pre-split bf16: C = A @ B^T. Block 128x128, 8 warps (64x32),
// K-chunk 16, x3 split terms, register-prefetched smem fill.
// ---------------------------------------------------------------------------
#define SMP 24

#define TC_GEMM_BODY(AH, AL, BH, BL)                                          \
    __shared__ __nv_bfloat16 sAh[128 * SMP], sAl[128 * SMP];                  \
    __shared__ __nv_bfloat16 sBh[128 * SMP], sBl[128 * SMP];                  \
    const int tid = threadIdx.x;                                              \
    const int wid = tid >> 5, lane = tid & 31;                                \
    const int m0 = blockIdx.y * 128, n0 = blockIdx.x * 128;                   \
    const int wm = (wid & 1) * 64;                                            \
    const int wn = (wid >> 1) * 32;                                           \
    float acc[4][4][4];                                                       \
    _Pragma("unroll")                                                         \
    for (int i = 0; i < 4; i++)                                               \
        _Pragma("unroll")                                                     \
        for (int j = 0; j < 4; j++)                                           \
            _Pragma("unroll")                                                 \
            for (int e = 0; e < 4; e++) acc[i][j][e] = 0.0f;                  \
    const int lrow = tid >> 1;        /* 0..127 */                            \
    const int lseg = (tid & 1) * 8;   /* col 0 or 8 */                        \
    const __nv_bfloat16* pah = (AH) + (size_t)(m0 + lrow) * CC + lseg;        \
    const __nv_bfloat16* pal = (AL) + (size_t)(m0 + lrow) * CC + lseg;        \
    const __nv_bfloat16* pbh = (BH) + (size_t)(n0 + lrow) * CC + lseg;        \
    const __nv_bfloat16* pbl = (BL) + (size_t)(n0 + lrow) * CC + lseg;        \
    uint4 rah = *(const uint4*)pah;                                           \
    uint4 ral = *(const uint4*)pal;                                           \
    uint4 rbh = *(const uint4*)pbh;                                           \
    uint4 rbl = *(const uint4*)pbl;                                           \
    _Pragma("unroll 1")                                                       \
    for (int k0 = 0; k0 < CC; k0 += 16) {                                     \
        *(uint4*)&sAh[lrow * SMP + lseg] = rah;                               \
        *(uint4*)&sAl[lrow * SMP + lseg] = ral;                               \
        *(uint4*)&sBh[lrow * SMP + lseg] = rbh;                               \
        *(uint4*)&sBl[lrow * SMP + lseg] = rbl;                               \
        __syncthreads();                                                      \
        if (k0 + 16 < CC) {                                                   \
            rah = *(const uint4*)(pah + k0 + 16);                             \
            ral = *(const uint4*)(pal + k0 + 16);                             \
            rbh = *(const uint4*)(pbh + k0 + 16);                             \
            rbl = *(const uint4*)(pbl + k0 + 16);                             \
        }                                                                     \
        uint32_t fbh[4][2], fbl[4][2];                                        \
        {                                                                     \
            int br = (lane & 7) + ((lane >> 1) & 8);  /* +8 for lanes>=16 */  \
            int bc = lane & 8;                                                \
            _Pragma("unroll")                                                 \
            for (int ntp = 0; ntp < 2; ntp++) {                               \
                uint32_t t4[4];                                               \
                ldm_x4(t4, &sBh[(wn + ntp * 16 + br) * SMP + bc]);            \
                fbh[2 * ntp][0] = t4[0]; fbh[2 * ntp][1] = t4[1];             \
                fbh[2 * ntp + 1][0] = t4[2]; fbh[2 * ntp + 1][1] = t4[3];     \
                ldm_x4(t4, &sBl[(wn + ntp * 16 + br) * SMP + bc]);            \
                fbl[2 * ntp][0] = t4[0]; fbl[2 * ntp][1] = t4[1];             \
                fbl[2 * ntp + 1][0] = t4[2]; fbl[2 * ntp + 1][1] = t4[3];     \
            }                                                                 \
        }                                                                     \
        {                                                                     \
            int mat = lane >> 3, rr = lane & 7;                               \
            int arow_off = (mat & 1) * 8 + rr;                                \
            int acol = (mat >> 1) * 8;                                        \
            _Pragma("unroll")                                                 \
            for (int mt = 0; mt < 4; mt++) {                                  \
                uint32_t fah[4], fal[4];                                      \
                int arow = wm + mt * 16 + arow_off;                           \
                ldm_x4(fah, &sAh[arow * SMP + acol]);                         \
                ldm_x4(fal, &sAl[arow * SMP + acol]);                         \
                _Pragma("unroll")                                             \
                for (int nt = 0; nt < 4; nt++) {                              \
                    mma_bf16(acc[mt][nt], fah, fbh[nt]);                      \
                    mma_bf16(acc[mt][nt], fah, fbl[nt]);                      \
                    mma_bf16(acc[mt][nt], fal, fbh[nt]);                      \
                }                                                             \
            }                                                                 \
        }                                                                     \
        __syncthreads();                                                      \
    }

// GEMM1: qkv. Q -> fp32 g_q; K,V -> bf16 hi/lo, all in [B,H,T,D]
__global__ __launch_bounds__(256) void qkv_gemm() {
    TC_GEMM_BODY(gXh, gXl, gWah, gWal)
    #pragma unroll
    for (int mt = 0; mt < 4; mt++) {
        #pragma unroll
        for (int nt = 0; nt < 4; nt++) {
            int n = n0 + wn + nt * 8 + (lane & 3) * 2;
            int sec = n / CC;               // 0=q 1=k 2=v
            int c2 = n - sec * CC;
            int h = c2 >> 6, d = c2 & 63;
            #pragma unroll
            for (int half = 0; half < 2; half++) {
                int m = m0 + wm + mt * 16 + (lane >> 2) + half * 8;
                int b = m >> 11, t = m & 2047;
                size_t idx = (size_t)((b * NH + h) * TT + t) * HD + d;
                float v0 = acc[mt][nt][half * 2 + 0];
                float v1 = acc[mt][nt][half * 2 + 1];
                if (sec == 0) {
                    *(float2*)&g_q[idx] = make_float2(v0, v1);
                } else {
                    uint32_t hh, ll;
                    split2(v0, v1, hh, ll);
                    if (sec == 1) {
                        *(uint32_t*)&g_kh[idx] = hh;
                        *(uint32_t*)&g_kl[idx] = ll;
                    } else {
                        *(uint32_t*)&g_vh[idx] = hh;
                        *(uint32_t*)&g_vl[idx] = ll;
                    }
                }
            }
        }
    }
}

// GEMM2: out = att @ W_proj^T (A pre-split by attention epilogue)
__global__ __launch_bounds__(256) void proj_gemm(float* __restrict__ out) {
    TC_GEMM_BODY(g_ath, g_atl, gWph, gWpl)
    #pragma unroll
    for (int mt = 0; mt < 4; mt++) {
        #pragma unroll
        for (int nt = 0; nt < 4; nt++) {
            int n = n0 + wn + nt * 8 + (lane & 3) * 2;
            #pragma unroll
            for (int half = 0; half < 2; half++) {
                int m = m0 + wm + mt * 16 + (lane >> 2) + half * 8;
                float2 v2 = make_float2(acc[mt][nt][half * 2 + 0],
                                        acc[mt][nt][half * 2 + 1]);
                *(float2*)&out[(size_t)m * CC + n] = v2;
            }
        }
    }
}

// ---------------------------------------------------------------------------
// HMMA flash attention: Bq=64 (4 warps x 16 rows), Bk=64. K/V already bf16
// hi/lo in gmem -> smem fill is a pure copy. S/P in register fragments.
// ---------------------------------------------------------------------------
#define ATP 72

__global__ __launch_bounds__(128) void attn_kernel() {
    __shared__ __nv_bfloat16 sKh[64 * ATP], sKl[64 * ATP];
    __shared__ __nv_bfloat16 sVh[64 * ATP], sVl[64 * ATP];

    const int qt = gridDim.x - 1 - blockIdx.x;   // heavy blocks first
    const int bh = blockIdx.y;
    const int q0 = qt * 64;
    const int tid = threadIdx.x;
    const int warp = tid >> 5, lane = tid & 31;
    const size_t base = (size_t)bh * TT * HD;
    const float* qp = g_q + base;

    const int r = lane >> 2;
    const int c2 = (lane & 3) * 2;
    const float QS = 0.125f;

    // Q fragments (A-layout, 4 k-chunks over HD=64), hi/lo, from gmem
    uint32_t qfh[4][4], qfl[4][4];
    #pragma unroll
    for (int kc = 0; kc < 4; kc++) {
        #pragma unroll
        for (int e = 0; e < 4; e++) {
            int row = q0 + warp * 16 + r + ((e & 1) ? 8 : 0);
            int col = kc * 16 + c2 + ((e & 2) ? 8 : 0);
            float2 v = *(const float2*)&qp[(size_t)row * HD + col];
            split2(v.x * QS, v.y * QS, qfh[kc][e], qfl[kc][e]);
        }
    }

    float mi[2] = {-1e30f, -1e30f};
    float li[2] = {0.0f, 0.0f};
    float o[8][4];
    #pragma unroll
    for (int nt = 0; nt < 8; nt++)
        #pragma unroll
        for (int e = 0; e < 4; e++) o[nt][e] = 0.0f;

    const int frow = tid >> 1;          // 0..63
    const int fcb  = (tid & 1) * 32;    // col half

    for (int kt = 0; kt <= qt; kt++) {
        const int k0 = kt * 64;

        // ---- copy bf16 K/V tiles into smem (no conversion) ----
        {
            size_t g = base + (size_t)(k0 + frow) * HD + fcb;
            #pragma unroll
            for (int u = 0; u < 4; u++) {
                *(uint4*)&sKh[frow * ATP + fcb + u * 8] = *(const uint4*)&g_kh[g + u * 8];
                *(uint4*)&sKl[frow * ATP + fcb + u * 8] = *(const uint4*)&g_kl[g + u * 8];
                *(uint4*)&sVh[frow * ATP + fcb + u * 8] = *(const uint4*)&g_vh[g + u * 8];
                *(uint4*)&sVl[frow * ATP + fcb + u * 8] = *(const uint4*)&g_vl[g + u * 8];
            }
        }
        __syncthreads();

        // ---- S = Q @ K^T ----
        float s[8][4];
        #pragma unroll
        for (int nt = 0; nt < 8; nt++)
            #pragma unroll
            for (int e = 0; e < 4; e++) s[nt][e] = 0.0f;

        {
            int br = (lane & 7) + ((lane >> 1) & 8);
            int bc = lane & 8;
            #pragma unroll
            for (int ntp = 0; ntp < 4; ntp++) {
                #pragma unroll
                for (int kc = 0; kc < 4; kc++) {
                    uint32_t kh4[4], kl4[4];
                    ldm_x4(kh4, &sKh[(ntp * 16 + br) * ATP + kc * 16 + bc]);
                    ldm_x4(kl4, &sKl[(ntp * 16 + br) * ATP + kc * 16 + bc]);
                    mma_bf16(s[2 * ntp],     qfh[kc], kh4);
                    mma_bf16(s[2 * ntp],     qfh[kc], kl4);
                    mma_bf16(s[2 * ntp],     qfl[kc], kh4);
                    mma_bf16(s[2 * ntp + 1], qfh[kc], kh4 + 2);
                    mma_bf16(s[2 * ntp + 1], qfh[kc], kl4 + 2);
                    mma_bf16(s[2 * ntp + 1], qfl[kc], kh4 + 2);
                }
            }
        }

        // ---- causal mask on diagonal tile ----
        if (kt == qt) {
            const int row0 = q0 + warp * 16 + r;
            #pragma unroll
            for (int nt = 0; nt < 8; nt++) {
                int colb = k0 + nt * 8 + c2;
                if (colb     > row0)     s[nt][0] = -1e30f;
                if (colb + 1 > row0)     s[nt][1] = -1e30f;
                if (colb     > row0 + 8) s[nt][2] = -1e30f;
                if (colb + 1 > row0 + 8) s[nt][3] = -1e30f;
            }
        }

        // ---- online softmax ----
        #pragma unroll
        for (int h = 0; h < 2; h++) {
            float m = -1e30f;
            #pragma unroll
            for (int nt = 0; nt < 8; nt++)
                m = fmaxf(m, fmaxf(s[nt][h * 2], s[nt][h * 2 + 1]));
            m = fmaxf(m, __shfl_xor_sync(0xffffffffu, m, 1));
            m = fmaxf(m, __shfl_xor_sync(0xffffffffu, m, 2));
            float mnew = fmaxf(mi[h], m);
            float alpha = __expf(mi[h] - mnew);
            float sum = 0.0f;
            #pragma unroll
            for (int nt = 0; nt < 8; nt++) {
                s[nt][h * 2]     = __expf(s[nt][h * 2] - mnew);
                s[nt][h * 2 + 1] = __expf(s[nt][h * 2 + 1] - mnew);
                sum += s[nt][h * 2] + s[nt][h * 2 + 1];
            }
            sum += __shfl_xor_sync(0xffffffffu, sum, 1);
            sum += __shfl_xor_sync(0xffffffffu, sum, 2);
            li[h] = li[h] * alpha + sum;
            mi[h] = mnew;
            #pragma unroll
            for (int nt = 0; nt < 8; nt++) {
                o[nt][h * 2]     *= alpha;
                o[nt][h * 2 + 1] *= alpha;
            }
        }

        // ---- P to A-fragments, hi/lo split ----
        uint32_t pfh[4][4], pfl[4][4];
        #pragma unroll
        for (int kc = 0; kc < 4; kc++) {
            split2(s[2 * kc][0],     s[2 * kc][1],     pfh[kc][0], pfl[kc][0]);
            split2(s[2 * kc][2],     s[2 * kc][3],     pfh[kc][1], pfl[kc][1]);
            split2(s[2 * kc + 1][0], s[2 * kc + 1][1], pfh[kc][2], pfl[kc][2]);
            split2(s[2 * kc + 1][2], s[2 * kc + 1][3], pfh[kc][3], pfl[kc][3]);
        }

        // ---- O += P @ V ----
        {
            const int vr = lane & 15;
            #pragma unroll
            for (int nt = 0; nt < 8; nt++) {
                #pragma unroll
                for (int kc = 0; kc < 4; kc++) {
                    uint32_t vh[2], vl[2];
                    ldm_x2_trans(vh, &sVh[(kc * 16 + vr) * ATP + nt * 8]);
                    ldm_x2_trans(vl, &sVl[(kc * 16 + vr) * ATP + nt * 8]);
                    mma_bf16(o[nt], pfh[kc], vh);
                    mma_bf16(o[nt], pfh[kc], vl);
                    mma_bf16(o[nt], pfl[kc], vh);
                }
            }
        }
        __syncthreads();
    }

    // ---- epilogue: normalize, split, write bf16 hi/lo [B,T,C] ----
    const int b = bh / NH, head = bh % NH;
    #pragma unroll
    for (int h = 0; h < 2; h++) {
        float inv = 1.0f / li[h];
        int row = q0 + warp * 16 + r + h * 8;
        size_t doff = (size_t)(b * TT + row) * CC + head * HD;
        #pragma unroll
        for (int nt = 0; nt < 8; nt++) {
            uint32_t hh, ll;
            split2(o[nt][h * 2] * inv, o[nt][h * 2 + 1] * inv, hh, ll);
            *(uint32_t*)&g_ath[doff + nt * 8 + c2] = hh;
            *(uint32_t*)&g_atl[doff + nt * 8 + c2] = ll;
        }
    }
}

// ---------------------------------------------------------------------------
extern "C" void kernel_launch(void* const* d_in, const int* in_sizes, int n_in,
                              void* d_out, int out_size) {
    const float* x  = (const float*)d_in[0];   // [2,2048,768]
    const float* Wa = (const float*)d_in[1];   // [2304,768]
    const float* Wp = (const float*)d_in[2];   // [768,768]
    float* out = (float*)d_out;                // [2,2048,768]

    __nv_bfloat16 *xh, *xl, *wah, *wal, *wph, *wpl;
    cudaGetSymbolAddress((void**)&xh,  gXh);
    cudaGetSymbolAddress((void**)&xl,  gXl);
    cudaGetSymbolAddress((void**)&wah, gWah);
    cudaGetSymbolAddress((void**)&wal, gWal);
    cudaGetSymbolAddress((void**)&wph, gWph);
    cudaGetSymbolAddress((void**)&wpl, gWpl);

    split_pass<<<(MQ * CC / 4 + 255) / 256, 256>>>(x, xh, xl, MQ * CC / 4);
    split_pass<<<(3 * CC * CC / 4 + 255) / 256, 256>>>(Wa, wah, wal, 3 * CC * CC / 4);
    split_pass<<<(CC * CC / 4 + 255) / 256, 256>>>(Wp, wph, wpl, CC * CC / 4);

    // QKV: M=4096 (32 tiles), N=2304 (18 tiles)
    qkv_gemm<<<dim3(18, 32), 256>>>();

    // Attention: 32 q-tiles x 24 (b,h)
    attn_kernel<<<dim3(32, 24), 128>>>();

    // Proj: M=4096 (32 tiles), N=768 (6 tiles)
    proj_gemm<<<dim3(6, 32), 256>>>(out);
}